// round 16
// baseline (speedup 1.0000x reference)
#include <cuda_runtime.h>
#include <cuda_fp16.h>

#define N_NODES 50000
#define N_EDGES 800000
#define E_TOT   850000
#define N_GRAPHS 256
#define NEG_SLOPE 0.2f

// ---------------- scratch ----------------
__device__ int    g_deg   [N_NODES];       // INVARIANT: zero at kernel_launch entry
__device__ int    g_rowptr[N_NODES + 1];
__device__ int    g_rank  [N_EDGES];       // packed: dst | (rank<<16)
__device__ int    g_col   [E_TOT];
__device__ int    g_bsum  [256];
__device__ int    g_gstart[N_GRAPHS + 1];  // per-graph node range
__device__ float  g_proj  [16];            // psa[4], psb[4], pda[4], pdb[4]

__device__ float2 g_e1s[N_NODES * 4];      // (exp(as), exp(0.2*as)) per node,head
__device__ float2 g_e1d[N_NODES * 4];
__device__ __half g_h2 [N_NODES * 32];     // [N,32] fp16 layer-2 features
__device__ float2 g_e2s[N_NODES];
__device__ float2 g_e2d[N_NODES];
__device__ float  g_pool[N_GRAPHS * 32];   // INVARIANT: zero at kernel_launch entry

#define HIST_THREADS 200000                // N_EDGES/4 threads, 4 edges each

__device__ __forceinline__ float elu1(float v) {
    return v > 0.f ? v : (__expf(v) - 1.f);
}

// --- hist over dst (4 edges/thread, packed dst|rank) + W1/a projections -------
__global__ void k_hist(const int* __restrict__ ei, const float* __restrict__ W1,
                       const float* __restrict__ as1, const float* __restrict__ ad1)
{
    int t = blockIdx.x * blockDim.x + threadIdx.x;
    if (t < HIST_THREADS) {
#pragma unroll
        for (int k = 0; k < 4; k++) {
            int e = t + k * HIST_THREADS;
            int d = ei[N_EDGES + e];
            int r = atomicAdd(&g_deg[d], 1);
            g_rank[e] = d | (r << 16);          // d < 50000 < 2^16; rank << 2^16
        }
    }

    if (blockIdx.x == 0 && threadIdx.x < 128) {
        int f = threadIdx.x, lane = f & 31, head = f >> 5;
        float w0 = W1[f], w1 = W1[128 + f];
        float a = as1[f], b = ad1[f];
        float p0 = w0 * a, p1 = w1 * a, p2 = w0 * b, p3 = w1 * b;
#pragma unroll
        for (int o = 16; o > 0; o >>= 1) {
            p0 += __shfl_down_sync(0xffffffffu, p0, o);
            p1 += __shfl_down_sync(0xffffffffu, p1, o);
            p2 += __shfl_down_sync(0xffffffffu, p2, o);
            p3 += __shfl_down_sync(0xffffffffu, p3, o);
        }
        if (lane == 0) {
            g_proj[head]      = p0;
            g_proj[4 + head]  = p1;
            g_proj[8 + head]  = p2;
            g_proj[12 + head] = p3;
        }
    }
}

// ---------------- scan phase 1 (block scan of deg) + layer-1 alphas -----------
__global__ void k_scan1(const float* __restrict__ x)
{
    __shared__ int wsum[8];
    int i = blockIdx.x * 256 + threadIdx.x;
    int v = 0;
    if (i < N_NODES) { v = g_deg[i] + 1; g_deg[i] = 0; }   // +1 self loop; restore zero
    int lane = threadIdx.x & 31, wp = threadIdx.x >> 5;
    int s = v;
#pragma unroll
    for (int o = 1; o < 32; o <<= 1) {
        int t = __shfl_up_sync(0xffffffffu, s, o);
        if (lane >= o) s += t;
    }
    if (lane == 31) wsum[wp] = s;

    if (i < N_NODES) {
        float2 xv = ((const float2*)x)[i];
#pragma unroll
        for (int h = 0; h < 4; h++) {
            float vs = xv.x * g_proj[h]     + xv.y * g_proj[4 + h];
            float vd = xv.x * g_proj[8 + h] + xv.y * g_proj[12 + h];
            g_e1s[i * 4 + h] = make_float2(__expf(vs), __expf(NEG_SLOPE * vs));
            g_e1d[i * 4 + h] = make_float2(__expf(vd), __expf(NEG_SLOPE * vd));
        }
    }

    __syncthreads();
    if (wp == 0) {
        int ws = (lane < 8) ? wsum[lane] : 0;
#pragma unroll
        for (int o = 1; o < 8; o <<= 1) {
            int t = __shfl_up_sync(0xffffffffu, ws, o);
            if (lane >= o) ws += t;
        }
        if (lane < 8) wsum[lane] = ws;
    }
    __syncthreads();
    int base = (wp > 0) ? wsum[wp - 1] : 0;
    int incl = s + base;
    if (i < N_NODES) g_rowptr[i] = incl - v;
    if (threadIdx.x == 255) g_bsum[blockIdx.x] = incl;
}

// ------- prep: bsum prefix + final rowptr; block 196 also builds gstart -------
__global__ void k_prep(const int* __restrict__ batch)
{
    __shared__ int ssum[8];
    int b = blockIdx.x;
    int t = threadIdx.x;
    int lane = t & 31, wp = t >> 5;

    int v = (t < b) ? g_bsum[t] : 0;
#pragma unroll
    for (int o = 16; o > 0; o >>= 1)
        v += __shfl_down_sync(0xffffffffu, v, o);
    if (lane == 0) ssum[wp] = v;
    __syncthreads();
    int base = ssum[0] + ssum[1] + ssum[2] + ssum[3]
             + ssum[4] + ssum[5] + ssum[6] + ssum[7];

    int i = b * 256 + t;
    if (i < N_NODES) g_rowptr[i] += base;
    if (i == N_NODES) g_rowptr[N_NODES] = E_TOT;

    if (b == 196) {
        int g = t;
        if (g < N_GRAPHS) {
            int lo = 0, hi = N_NODES;
            while (lo < hi) { int m = (lo + hi) >> 1; if (batch[m] < g) lo = m + 1; else hi = m; }
            g_gstart[g] = lo;
        }
        if (t == 0) g_gstart[N_GRAPHS] = N_NODES;
    }
}

// ---------- scatter: packed rank, no atomics, 1 edge/thread -------------------
__global__ void k_scatter(const int* __restrict__ ei)
{
    int t = blockIdx.x * blockDim.x + threadIdx.x;
    if (t < N_EDGES) {
        int p = g_rank[t];
        int d = p & 0xFFFF;
        int r = p >> 16;
        g_col[g_rowptr[d] + r] = ei[t];
    } else if (t < E_TOT) {
        int n = t - N_EDGES;                      // self loops
        g_col[g_rowptr[n + 1] - 1] = n;
    }
}

// -- gat1: quad gather (unroll x2) + cooperative matmul; occupancy-tuned -------
__global__ void __launch_bounds__(256, 6) k_gat1(
    const float* __restrict__ x, const float* __restrict__ W1,
    const float* __restrict__ W2, const float* __restrict__ b1,
    const float* __restrict__ as2, const float* __restrict__ ad2)
{
    __shared__ float W2k[128 * 32];     // k-major [k][c] (native W2 layout)
    __shared__ float act_s[8][128];     // per-warp act staging
    __shared__ float red_s[8][8][32];   // [node][kslice][channel] partials
    for (int i = threadIdx.x; i < 128 * 32; i += blockDim.x)
        W2k[i] = W2[i];
    __syncthreads();

    int lane = threadIdx.x & 31;
    int wrp  = threadIdx.x >> 5;
    int qh = lane & 3;                  // head for edge loop
    int e8 = lane >> 2;                 // edge slot 0..7
    int k0 = wrp * 16;                  // this warp's k-slice for the matmul

    for (int tile = blockIdx.x; tile < N_NODES / 8; tile += gridDim.x) {
        int node = tile * 8 + wrp;

        float2 ed = g_e1d[node * 4 + qh];
        int beg = g_rowptr[node], end = g_rowptr[node + 1];

        float sx0 = 0.f, sy0 = 0.f, dn0 = 0.f;
        float sx1 = 0.f, sy1 = 0.f, dn1 = 0.f;
        int j = beg + e8;
        for (; j + 8 < end; j += 16) {
            int s0 = g_col[j];
            int s1 = g_col[j + 8];
            float2 xs0 = ((const float2*)x)[s0];
            float2 xs1 = ((const float2*)x)[s1];
            float2 es0 = g_e1s[s0 * 4 + qh];
            float2 es1 = g_e1s[s1 * 4 + qh];
            float p0 = es0.x * ed.x, p1 = es1.x * ed.x;
            float w0 = (p0 > 1.f) ? p0 : es0.y * ed.y;
            float w1 = (p1 > 1.f) ? p1 : es1.y * ed.y;
            dn0 += w0; sx0 += w0 * xs0.x; sy0 += w0 * xs0.y;
            dn1 += w1; sx1 += w1 * xs1.x; sy1 += w1 * xs1.y;
        }
        if (j < end) {
            int s = g_col[j];
            float2 xs = ((const float2*)x)[s];
            float2 es = g_e1s[s * 4 + qh];
            float p = es.x * ed.x;
            float w = (p > 1.f) ? p : es.y * ed.y;
            dn0 += w; sx0 += w * xs.x; sy0 += w * xs.y;
        }
        float sx = sx0 + sx1, sy = sy0 + sy1, den = dn0 + dn1;

#pragma unroll
        for (int o = 4; o < 32; o <<= 1) {
            sx  += __shfl_xor_sync(0xffffffffu, sx,  o);
            sy  += __shfl_xor_sync(0xffffffffu, sy,  o);
            den += __shfl_xor_sync(0xffffffffu, den, o);
        }
        int src = lane >> 3;
        sx  = __shfl_sync(0xffffffffu, sx,  src);
        sy  = __shfl_sync(0xffffffffu, sy,  src);
        den = __shfl_sync(0xffffffffu, den, src);

        // constants loaded here (L1-resident) instead of hoisted — frees regs in gather
        float4 w1a = *(const float4*)&W1[lane * 4];
        float4 w1b = *(const float4*)&W1[128 + lane * 4];
        float4 b1v = *(const float4*)&b1[lane * 4];

        float inv = 1.f / (den + 1e-16f);
        float4 act;
        act.x = elu1((sx * w1a.x + sy * w1b.x) * inv + b1v.x);
        act.y = elu1((sx * w1a.y + sy * w1b.y) * inv + b1v.y);
        act.z = elu1((sx * w1a.z + sy * w1b.z) * inv + b1v.z);
        act.w = elu1((sx * w1a.w + sy * w1b.w) * inv + b1v.w);

        *(float4*)&act_s[wrp][lane * 4] = act;
        __syncthreads();                        // act ready for all warps

        // cooperative matmul: thread (kslice=wrp, c=lane) covers 16 k's for ALL 8 nodes
        float acc[8];
#pragma unroll
        for (int n = 0; n < 8; n++) acc[n] = 0.f;
#pragma unroll
        for (int kk = 0; kk < 16; kk += 4) {
            int k = k0 + kk;
            float w0 = W2k[(k + 0) * 32 + lane];   // coalesced, read ONCE per tile
            float w1 = W2k[(k + 1) * 32 + lane];
            float w2 = W2k[(k + 2) * 32 + lane];
            float w3 = W2k[(k + 3) * 32 + lane];
#pragma unroll
            for (int n = 0; n < 8; n++) {
                float4 a4 = *(const float4*)&act_s[n][k];   // broadcast
                acc[n] += a4.x * w0 + a4.y * w1 + a4.z * w2 + a4.w * w3;
            }
        }
#pragma unroll
        for (int n = 0; n < 8; n++)
            red_s[n][wrp][lane] = acc[n];
        __syncthreads();                        // partials ready

        // warp wrp finalizes node tile*8+wrp, channel lane
        float sum = red_s[wrp][0][lane] + red_s[wrp][1][lane]
                  + red_s[wrp][2][lane] + red_s[wrp][3][lane]
                  + red_s[wrp][4][lane] + red_s[wrp][5][lane]
                  + red_s[wrp][6][lane] + red_s[wrp][7][lane];

        g_h2[node * 32 + lane] = __float2half_rn(sum);

        float vs = sum * as2[lane];
        float vd = sum * ad2[lane];
#pragma unroll
        for (int o = 16; o > 0; o >>= 1) {
            vs += __shfl_down_sync(0xffffffffu, vs, o);
            vd += __shfl_down_sync(0xffffffffu, vd, o);
        }
        if (lane == 0) {
            g_e2s[node] = make_float2(__expf(vs), __expf(NEG_SLOPE * vs));
            g_e2d[node] = make_float2(__expf(vd), __expf(NEG_SLOPE * vd));
        }
    }
}

// ------ gat2: two half-warps, 4 edges in flight each, half2 channels ----------
__global__ void k_gat2(const int* __restrict__ batch, const float* __restrict__ b2)
{
    int lane = threadIdx.x & 31;
    int node = blockIdx.x * 8 + (threadIdx.x >> 5);
    int pr = lane >> 4;                 // half-warp (edge parity)
    int ch = lane & 15;                 // channel-pair index

    const __half2* h2p = (const __half2*)g_h2;
    float2 ed = g_e2d[node];
    float ax0 = 0.f, ay0 = 0.f, dn0 = 0.f;
    float ax1 = 0.f, ay1 = 0.f, dn1 = 0.f;
    int beg = g_rowptr[node], end = g_rowptr[node + 1];

    int j = beg + pr;
    for (; j + 6 < end; j += 8) {       // four edges in flight per half-warp
        int s0 = g_col[j],     s1 = g_col[j + 2];
        int s2 = g_col[j + 4], s3 = g_col[j + 6];
        float2 e0 = g_e2s[s0], e1 = g_e2s[s1], e2 = g_e2s[s2], e3 = g_e2s[s3];
        float2 h0 = __half22float2(h2p[s0 * 16 + ch]);
        float2 h1 = __half22float2(h2p[s1 * 16 + ch]);
        float2 h2v = __half22float2(h2p[s2 * 16 + ch]);
        float2 h3 = __half22float2(h2p[s3 * 16 + ch]);
        float p0 = e0.x * ed.x, p1 = e1.x * ed.x, p2 = e2.x * ed.x, p3 = e3.x * ed.x;
        float w0 = (p0 > 1.f) ? p0 : e0.y * ed.y;
        float w1 = (p1 > 1.f) ? p1 : e1.y * ed.y;
        float w2 = (p2 > 1.f) ? p2 : e2.y * ed.y;
        float w3 = (p3 > 1.f) ? p3 : e3.y * ed.y;
        ax0 += w0 * h0.x + w2 * h2v.x;  ay0 += w0 * h0.y + w2 * h2v.y;  dn0 += w0 + w2;
        ax1 += w1 * h1.x + w3 * h3.x;   ay1 += w1 * h1.y + w3 * h3.y;   dn1 += w1 + w3;
    }
    for (; j < end; j += 2) {
        int s = g_col[j];
        float2 es = g_e2s[s];
        float2 hf = __half22float2(h2p[s * 16 + ch]);
        float p = es.x * ed.x;
        float w = (p > 1.f) ? p : es.y * ed.y;
        ax0 += w * hf.x;
        ay0 += w * hf.y;
        dn0 += w;
    }
    float ax = ax0 + ax1, ay = ay0 + ay1, den = dn0 + dn1;
    ax  += __shfl_xor_sync(0xffffffffu, ax,  16);
    ay  += __shfl_xor_sync(0xffffffffu, ay,  16);
    den += __shfl_xor_sync(0xffffffffu, den, 16);

    float axx = __shfl_sync(0xffffffffu, ax, lane >> 1);
    float ayy = __shfl_sync(0xffffffffu, ay, lane >> 1);
    float accv = (lane & 1) ? ayy : axx;

    float v = elu1(accv / (den + 1e-16f) + b2[lane]);
    atomicAdd(&g_pool[batch[node] * 32 + lane], v);
}

// ------- final: mean pool + linear via precomputed ranges (re-zeroes pool) ----
__global__ void k_final(const float* __restrict__ Wlin, const float* __restrict__ blin,
                        float* __restrict__ out)
{
    int g = blockIdx.x;
    int c = threadIdx.x;

    int start = g_gstart[g];
    int cnt = g_gstart[g + 1] - start;

    float pv = g_pool[g * 32 + c];
    g_pool[g * 32 + c] = 0.f;

    float fc = (float)(cnt > 0 ? cnt : 1);
    float v = (pv / fc) * Wlin[c];
#pragma unroll
    for (int o = 16; o > 0; o >>= 1)
        v += __shfl_down_sync(0xffffffffu, v, o);
    if (c == 0) out[g] = v + blin[0];
}

// ---------------- launch ------------------------------------------------------
extern "C" void kernel_launch(void* const* d_in, const int* in_sizes, int n_in,
                              void* d_out, int out_size)
{
    const float* x     = (const float*)d_in[0];
    const int*   ei    = (const int*)  d_in[1];
    const int*   batch = (const int*)  d_in[2];
    const float* W1    = (const float*)d_in[3];
    const float* as1   = (const float*)d_in[4];
    const float* ad1   = (const float*)d_in[5];
    const float* b1    = (const float*)d_in[6];
    const float* W2    = (const float*)d_in[7];
    const float* as2   = (const float*)d_in[8];
    const float* ad2   = (const float*)d_in[9];
    const float* b2    = (const float*)d_in[10];
    const float* Wlin  = (const float*)d_in[11];
    const float* blin  = (const float*)d_in[12];
    float* out = (float*)d_out;

    k_hist<<<(HIST_THREADS + 255) / 256, 256>>>(ei, W1, as1, ad1);
    k_scan1<<<196, 256>>>(x);
    k_prep<<<197, 256>>>(batch);
    k_scatter<<<(E_TOT + 255) / 256, 256>>>(ei);
    k_gat1<<<1184, 256>>>(x, W1, W2, b1, as2, ad2);
    k_gat2<<<6250, 256>>>(batch, b2);
    k_final<<<N_GRAPHS, 32>>>(Wlin, blin, out);
}

// round 17
// speedup vs baseline: 1.0638x; 1.0638x over previous
#include <cuda_runtime.h>
#include <cuda_fp16.h>

#define N_NODES 50000
#define N_EDGES 800000
#define E_TOT   850000
#define N_GRAPHS 256
#define NEG_SLOPE 0.2f

// ---------------- scratch ----------------
__device__ int    g_deg   [N_NODES];       // INVARIANT: zero at kernel_launch entry
__device__ int    g_rowptr[N_NODES + 1];
__device__ int    g_rank  [N_EDGES];       // packed: dst | (rank<<16)
__device__ int    g_col   [E_TOT];
__device__ int    g_bsum  [256];
__device__ int    g_gstart[N_GRAPHS + 1];  // per-graph node range
__device__ float  g_proj  [16];            // psa[4], psb[4], pda[4], pdb[4]

__device__ float2 g_e1s[N_NODES * 4];      // (exp(as), exp(0.2*as)) per node,head
__device__ float2 g_e1d[N_NODES * 4];
__device__ __half g_h2 [N_NODES * 32];     // [N,32] fp16 layer-2 features
__device__ float2 g_e2s[N_NODES];
__device__ float2 g_e2d[N_NODES];
__device__ float  g_pool[N_GRAPHS * 32];   // INVARIANT: zero at kernel_launch entry

#define HIST_THREADS 200000                // N_EDGES/4 threads, 4 edges each

__device__ __forceinline__ float elu1(float v) {
    return v > 0.f ? v : (__expf(v) - 1.f);
}

// --- hist over dst (4 edges/thread, packed dst|rank) + W1/a projections -------
__global__ void k_hist(const int* __restrict__ ei, const float* __restrict__ W1,
                       const float* __restrict__ as1, const float* __restrict__ ad1)
{
    int t = blockIdx.x * blockDim.x + threadIdx.x;
    if (t < HIST_THREADS) {
#pragma unroll
        for (int k = 0; k < 4; k++) {
            int e = t + k * HIST_THREADS;
            int d = ei[N_EDGES + e];
            int r = atomicAdd(&g_deg[d], 1);
            g_rank[e] = d | (r << 16);          // d < 50000 < 2^16; rank << 2^16
        }
    }

    if (blockIdx.x == 0 && threadIdx.x < 128) {
        int f = threadIdx.x, lane = f & 31, head = f >> 5;
        float w0 = W1[f], w1 = W1[128 + f];
        float a = as1[f], b = ad1[f];
        float p0 = w0 * a, p1 = w1 * a, p2 = w0 * b, p3 = w1 * b;
#pragma unroll
        for (int o = 16; o > 0; o >>= 1) {
            p0 += __shfl_down_sync(0xffffffffu, p0, o);
            p1 += __shfl_down_sync(0xffffffffu, p1, o);
            p2 += __shfl_down_sync(0xffffffffu, p2, o);
            p3 += __shfl_down_sync(0xffffffffu, p3, o);
        }
        if (lane == 0) {
            g_proj[head]      = p0;
            g_proj[4 + head]  = p1;
            g_proj[8 + head]  = p2;
            g_proj[12 + head] = p3;
        }
    }
}

// ---------------- scan phase 1 (block scan of deg) + layer-1 alphas -----------
__global__ void k_scan1(const float* __restrict__ x)
{
    __shared__ int wsum[8];
    int i = blockIdx.x * 256 + threadIdx.x;
    int v = 0;
    if (i < N_NODES) { v = g_deg[i] + 1; g_deg[i] = 0; }   // +1 self loop; restore zero
    int lane = threadIdx.x & 31, wp = threadIdx.x >> 5;
    int s = v;
#pragma unroll
    for (int o = 1; o < 32; o <<= 1) {
        int t = __shfl_up_sync(0xffffffffu, s, o);
        if (lane >= o) s += t;
    }
    if (lane == 31) wsum[wp] = s;

    if (i < N_NODES) {
        float2 xv = ((const float2*)x)[i];
#pragma unroll
        for (int h = 0; h < 4; h++) {
            float vs = xv.x * g_proj[h]     + xv.y * g_proj[4 + h];
            float vd = xv.x * g_proj[8 + h] + xv.y * g_proj[12 + h];
            g_e1s[i * 4 + h] = make_float2(__expf(vs), __expf(NEG_SLOPE * vs));
            g_e1d[i * 4 + h] = make_float2(__expf(vd), __expf(NEG_SLOPE * vd));
        }
    }

    __syncthreads();
    if (wp == 0) {
        int ws = (lane < 8) ? wsum[lane] : 0;
#pragma unroll
        for (int o = 1; o < 8; o <<= 1) {
            int t = __shfl_up_sync(0xffffffffu, ws, o);
            if (lane >= o) ws += t;
        }
        if (lane < 8) wsum[lane] = ws;
    }
    __syncthreads();
    int base = (wp > 0) ? wsum[wp - 1] : 0;
    int incl = s + base;
    if (i < N_NODES) g_rowptr[i] = incl - v;
    if (threadIdx.x == 255) g_bsum[blockIdx.x] = incl;
}

// ------- prep: bsum prefix + final rowptr; block 196 also builds gstart -------
__global__ void k_prep(const int* __restrict__ batch)
{
    __shared__ int ssum[8];
    int b = blockIdx.x;
    int t = threadIdx.x;
    int lane = t & 31, wp = t >> 5;

    int v = (t < b) ? g_bsum[t] : 0;
#pragma unroll
    for (int o = 16; o > 0; o >>= 1)
        v += __shfl_down_sync(0xffffffffu, v, o);
    if (lane == 0) ssum[wp] = v;
    __syncthreads();
    int base = ssum[0] + ssum[1] + ssum[2] + ssum[3]
             + ssum[4] + ssum[5] + ssum[6] + ssum[7];

    int i = b * 256 + t;
    if (i < N_NODES) g_rowptr[i] += base;
    if (i == N_NODES) g_rowptr[N_NODES] = E_TOT;

    if (b == 196) {
        int g = t;
        if (g < N_GRAPHS) {
            int lo = 0, hi = N_NODES;
            while (lo < hi) { int m = (lo + hi) >> 1; if (batch[m] < g) lo = m + 1; else hi = m; }
            g_gstart[g] = lo;
        }
        if (t == 0) g_gstart[N_GRAPHS] = N_NODES;
    }
}

// ---------- scatter: packed rank, no atomics, 1 edge/thread -------------------
__global__ void k_scatter(const int* __restrict__ ei)
{
    int t = blockIdx.x * blockDim.x + threadIdx.x;
    if (t < N_EDGES) {
        int p = g_rank[t];
        int d = p & 0xFFFF;
        int r = p >> 16;
        g_col[g_rowptr[d] + r] = ei[t];
    } else if (t < E_TOT) {
        int n = t - N_EDGES;                      // self loops
        g_col[g_rowptr[n + 1] - 1] = n;
    }
}

// -- gat1: quad gather (unroll x2) + BLOCK-COOPERATIVE matmul (R14 100.4µs ver)
__global__ void __launch_bounds__(256) k_gat1(
    const float* __restrict__ x, const float* __restrict__ W1,
    const float* __restrict__ W2, const float* __restrict__ b1,
    const float* __restrict__ as2, const float* __restrict__ ad2)
{
    __shared__ float W2k[128 * 32];     // k-major [k][c] (native W2 layout)
    __shared__ float act_s[8][128];     // per-warp act staging
    __shared__ float red_s[8][8][32];   // [node][kslice][channel] partials
    for (int i = threadIdx.x; i < 128 * 32; i += blockDim.x)
        W2k[i] = W2[i];
    __syncthreads();

    int lane = threadIdx.x & 31;
    int wrp  = threadIdx.x >> 5;
    int qh = lane & 3;                  // head for edge loop
    int e8 = lane >> 2;                 // edge slot 0..7

    float4 w1a = *(const float4*)&W1[lane * 4];
    float4 w1b = *(const float4*)&W1[128 + lane * 4];
    float4 b1v = *(const float4*)&b1[lane * 4];
    float asv = as2[lane];
    float adv = ad2[lane];
    int k0 = wrp * 16;                  // this warp's k-slice for the matmul

    for (int tile = blockIdx.x; tile < N_NODES / 8; tile += gridDim.x) {
        int node = tile * 8 + wrp;

        float2 ed = g_e1d[node * 4 + qh];
        int beg = g_rowptr[node], end = g_rowptr[node + 1];

        float sx0 = 0.f, sy0 = 0.f, dn0 = 0.f;
        float sx1 = 0.f, sy1 = 0.f, dn1 = 0.f;
        int j = beg + e8;
        for (; j + 8 < end; j += 16) {
            int s0 = g_col[j];
            int s1 = g_col[j + 8];
            float2 xs0 = ((const float2*)x)[s0];
            float2 xs1 = ((const float2*)x)[s1];
            float2 es0 = g_e1s[s0 * 4 + qh];
            float2 es1 = g_e1s[s1 * 4 + qh];
            float p0 = es0.x * ed.x, p1 = es1.x * ed.x;
            float w0 = (p0 > 1.f) ? p0 : es0.y * ed.y;
            float w1 = (p1 > 1.f) ? p1 : es1.y * ed.y;
            dn0 += w0; sx0 += w0 * xs0.x; sy0 += w0 * xs0.y;
            dn1 += w1; sx1 += w1 * xs1.x; sy1 += w1 * xs1.y;
        }
        if (j < end) {
            int s = g_col[j];
            float2 xs = ((const float2*)x)[s];
            float2 es = g_e1s[s * 4 + qh];
            float p = es.x * ed.x;
            float w = (p > 1.f) ? p : es.y * ed.y;
            dn0 += w; sx0 += w * xs.x; sy0 += w * xs.y;
        }
        float sx = sx0 + sx1, sy = sy0 + sy1, den = dn0 + dn1;

#pragma unroll
        for (int o = 4; o < 32; o <<= 1) {
            sx  += __shfl_xor_sync(0xffffffffu, sx,  o);
            sy  += __shfl_xor_sync(0xffffffffu, sy,  o);
            den += __shfl_xor_sync(0xffffffffu, den, o);
        }
        int src = lane >> 3;
        sx  = __shfl_sync(0xffffffffu, sx,  src);
        sy  = __shfl_sync(0xffffffffu, sy,  src);
        den = __shfl_sync(0xffffffffu, den, src);

        float inv = 1.f / (den + 1e-16f);
        float4 act;
        act.x = elu1((sx * w1a.x + sy * w1b.x) * inv + b1v.x);
        act.y = elu1((sx * w1a.y + sy * w1b.y) * inv + b1v.y);
        act.z = elu1((sx * w1a.z + sy * w1b.z) * inv + b1v.z);
        act.w = elu1((sx * w1a.w + sy * w1b.w) * inv + b1v.w);

        *(float4*)&act_s[wrp][lane * 4] = act;
        __syncthreads();                        // act ready for all warps

        // cooperative matmul: thread (kslice=wrp, c=lane) covers 16 k's for ALL 8 nodes
        float acc[8];
#pragma unroll
        for (int n = 0; n < 8; n++) acc[n] = 0.f;
#pragma unroll
        for (int kk = 0; kk < 16; kk += 4) {
            int k = k0 + kk;
            float w0 = W2k[(k + 0) * 32 + lane];   // coalesced, read ONCE per tile
            float w1 = W2k[(k + 1) * 32 + lane];
            float w2 = W2k[(k + 2) * 32 + lane];
            float w3 = W2k[(k + 3) * 32 + lane];
#pragma unroll
            for (int n = 0; n < 8; n++) {
                float4 a4 = *(const float4*)&act_s[n][k];   // broadcast
                acc[n] += a4.x * w0 + a4.y * w1 + a4.z * w2 + a4.w * w3;
            }
        }
#pragma unroll
        for (int n = 0; n < 8; n++)
            red_s[n][wrp][lane] = acc[n];
        __syncthreads();                        // partials ready

        // warp wrp finalizes node tile*8+wrp, channel lane
        float sum = red_s[wrp][0][lane] + red_s[wrp][1][lane]
                  + red_s[wrp][2][lane] + red_s[wrp][3][lane]
                  + red_s[wrp][4][lane] + red_s[wrp][5][lane]
                  + red_s[wrp][6][lane] + red_s[wrp][7][lane];

        g_h2[node * 32 + lane] = __float2half_rn(sum);

        float vs = sum * asv;
        float vd = sum * adv;
#pragma unroll
        for (int o = 16; o > 0; o >>= 1) {
            vs += __shfl_down_sync(0xffffffffu, vs, o);
            vd += __shfl_down_sync(0xffffffffu, vd, o);
        }
        if (lane == 0) {
            g_e2s[node] = make_float2(__expf(vs), __expf(NEG_SLOPE * vs));
            g_e2d[node] = make_float2(__expf(vd), __expf(NEG_SLOPE * vd));
        }
    }
}

// ------ gat2: two half-warps, 4 edges in flight each, half2 channels ----------
__global__ void k_gat2(const int* __restrict__ batch, const float* __restrict__ b2)
{
    int lane = threadIdx.x & 31;
    int node = blockIdx.x * 8 + (threadIdx.x >> 5);
    int pr = lane >> 4;                 // half-warp (edge parity)
    int ch = lane & 15;                 // channel-pair index

    const __half2* h2p = (const __half2*)g_h2;
    float2 ed = g_e2d[node];
    float ax0 = 0.f, ay0 = 0.f, dn0 = 0.f;
    float ax1 = 0.f, ay1 = 0.f, dn1 = 0.f;
    int beg = g_rowptr[node], end = g_rowptr[node + 1];

    int j = beg + pr;
    for (; j + 6 < end; j += 8) {       // four edges in flight per half-warp
        int s0 = g_col[j],     s1 = g_col[j + 2];
        int s2 = g_col[j + 4], s3 = g_col[j + 6];
        float2 e0 = g_e2s[s0], e1 = g_e2s[s1], e2 = g_e2s[s2], e3 = g_e2s[s3];
        float2 h0 = __half22float2(h2p[s0 * 16 + ch]);
        float2 h1 = __half22float2(h2p[s1 * 16 + ch]);
        float2 h2v = __half22float2(h2p[s2 * 16 + ch]);
        float2 h3 = __half22float2(h2p[s3 * 16 + ch]);
        float p0 = e0.x * ed.x, p1 = e1.x * ed.x, p2 = e2.x * ed.x, p3 = e3.x * ed.x;
        float w0 = (p0 > 1.f) ? p0 : e0.y * ed.y;
        float w1 = (p1 > 1.f) ? p1 : e1.y * ed.y;
        float w2 = (p2 > 1.f) ? p2 : e2.y * ed.y;
        float w3 = (p3 > 1.f) ? p3 : e3.y * ed.y;
        ax0 += w0 * h0.x + w2 * h2v.x;  ay0 += w0 * h0.y + w2 * h2v.y;  dn0 += w0 + w2;
        ax1 += w1 * h1.x + w3 * h3.x;   ay1 += w1 * h1.y + w3 * h3.y;   dn1 += w1 + w3;
    }
    for (; j < end; j += 2) {
        int s = g_col[j];
        float2 es = g_e2s[s];
        float2 hf = __half22float2(h2p[s * 16 + ch]);
        float p = es.x * ed.x;
        float w = (p > 1.f) ? p : es.y * ed.y;
        ax0 += w * hf.x;
        ay0 += w * hf.y;
        dn0 += w;
    }
    float ax = ax0 + ax1, ay = ay0 + ay1, den = dn0 + dn1;
    ax  += __shfl_xor_sync(0xffffffffu, ax,  16);
    ay  += __shfl_xor_sync(0xffffffffu, ay,  16);
    den += __shfl_xor_sync(0xffffffffu, den, 16);

    float axx = __shfl_sync(0xffffffffu, ax, lane >> 1);
    float ayy = __shfl_sync(0xffffffffu, ay, lane >> 1);
    float accv = (lane & 1) ? ayy : axx;

    float v = elu1(accv / (den + 1e-16f) + b2[lane]);
    atomicAdd(&g_pool[batch[node] * 32 + lane], v);
}

// ------- final: mean pool + linear via precomputed ranges (re-zeroes pool) ----
__global__ void k_final(const float* __restrict__ Wlin, const float* __restrict__ blin,
                        float* __restrict__ out)
{
    int g = blockIdx.x;
    int c = threadIdx.x;

    int start = g_gstart[g];
    int cnt = g_gstart[g + 1] - start;

    float pv = g_pool[g * 32 + c];
    g_pool[g * 32 + c] = 0.f;

    float fc = (float)(cnt > 0 ? cnt : 1);
    float v = (pv / fc) * Wlin[c];
#pragma unroll
    for (int o = 16; o > 0; o >>= 1)
        v += __shfl_down_sync(0xffffffffu, v, o);
    if (c == 0) out[g] = v + blin[0];
}

// ---------------- launch ------------------------------------------------------
extern "C" void kernel_launch(void* const* d_in, const int* in_sizes, int n_in,
                              void* d_out, int out_size)
{
    const float* x     = (const float*)d_in[0];
    const int*   ei    = (const int*)  d_in[1];
    const int*   batch = (const int*)  d_in[2];
    const float* W1    = (const float*)d_in[3];
    const float* as1   = (const float*)d_in[4];
    const float* ad1   = (const float*)d_in[5];
    const float* b1    = (const float*)d_in[6];
    const float* W2    = (const float*)d_in[7];
    const float* as2   = (const float*)d_in[8];
    const float* ad2   = (const float*)d_in[9];
    const float* b2    = (const float*)d_in[10];
    const float* Wlin  = (const float*)d_in[11];
    const float* blin  = (const float*)d_in[12];
    float* out = (float*)d_out;

    k_hist<<<(HIST_THREADS + 255) / 256, 256>>>(ei, W1, as1, ad1);
    k_scan1<<<196, 256>>>(x);
    k_prep<<<197, 256>>>(batch);
    k_scatter<<<(E_TOT + 255) / 256, 256>>>(ei);
    k_gat1<<<1184, 256>>>(x, W1, W2, b1, as2, ad2);
    k_gat2<<<6250, 256>>>(batch, b2);
    k_final<<<N_GRAPHS, 32>>>(Wlin, blin, out);
}